// round 1
// baseline (speedup 1.0000x reference)
#include <cuda_runtime.h>
#include <cuda_bf16.h>
#include <math.h>

// Problem constants
#define BB 2
#define LL 2048
#define SS 2048
#define HH 8
#define EE 64
#define NTOK (BB * SS * HH)          // 32768

// qev buffer: quantum-encoded values, layout identical to values [B,S,H,E]
__device__ float g_qev[(size_t)NTOK * EE];

// ---------------------------------------------------------------------------
// Quantum circuit helpers (4 qubits, 16 complex amplitudes, wire 0 = MSB)
// ---------------------------------------------------------------------------
template <int W>
__device__ __forceinline__ void apply_ry(float* ar, float* ai, float th) {
    float s, c;
    __sincosf(th * 0.5f, &s, &c);
    const int mask = 8 >> W;
#pragma unroll
    for (int i = 0; i < 16; i++) {
        if ((i & mask) == 0) {
            const int j = i | mask;
            float r0 = ar[i], i0 = ai[i], r1 = ar[j], i1 = ai[j];
            ar[i] = c * r0 - s * r1;  ai[i] = c * i0 - s * i1;
            ar[j] = s * r0 + c * r1;  ai[j] = s * i0 + c * i1;
        }
    }
}

template <int C, int T>
__device__ __forceinline__ void apply_crx(float* ar, float* ai, float th) {
    float s, c;
    __sincosf(th * 0.5f, &s, &c);
    const int cm = 8 >> C, tm = 8 >> T;
#pragma unroll
    for (int i = 0; i < 16; i++) {
        if ((i & cm) != 0 && (i & tm) == 0) {
            const int j = i | tm;
            float r0 = ar[i], i0 = ai[i], r1 = ar[j], i1 = ai[j];
            // new0 = c*a0 - i*s*a1 ; new1 = -i*s*a0 + c*a1
            ar[i] = c * r0 + s * i1;  ai[i] = c * i0 - s * r1;
            ar[j] = c * r1 + s * i0;  ai[j] = c * i1 - s * r0;
        }
    }
}

template <int W>
__device__ __forceinline__ void measure_xyz_w(const float* ar, const float* ai,
                                              float* meas) {
    const int mask = 8 >> W;
    float pr = 0.f, pi = 0.f, z = 0.f;
#pragma unroll
    for (int i = 0; i < 16; i++) {
        if ((i & mask) == 0) {
            const int j = i | mask;
            // conj(s0)*s1
            pr += ar[i] * ar[j] + ai[i] * ai[j];
            pi += ar[i] * ai[j] - ai[i] * ar[j];
            z  += ar[i] * ar[i] + ai[i] * ai[i]
                - ar[j] * ar[j] - ai[j] * ai[j];
        }
    }
    meas[W]     = 2.0f * pr;
    meas[4 + W] = 2.0f * pi;
    meas[8 + W] = z;
}

// ---------------------------------------------------------------------------
// Kernel 1: values -> angles -> PQC -> Pauli expvals -> qev  (one thread/token)
// ---------------------------------------------------------------------------
__global__ __launch_bounds__(256) void quantum_kernel(
    const float* __restrict__ values, const float* __restrict__ W_ang,
    const float* __restrict__ b_ang, const float* __restrict__ W_out,
    const float* __restrict__ b_out) {
    __shared__ float sW[16 * 64];
    __shared__ float sb[16];
    __shared__ float sWo[64 * 12];
    __shared__ float sbo[64];
    int tid = threadIdx.x;
    for (int i = tid; i < 16 * 64; i += 256) sW[i] = W_ang[i];
    for (int i = tid; i < 64 * 12; i += 256) sWo[i] = W_out[i];
    if (tid < 16) sb[tid] = b_ang[tid];
    if (tid < 64) sbo[tid] = b_out[tid];
    __syncthreads();

    int t = blockIdx.x * 256 + tid;   // token id, grid sized exactly NTOK/256
    const float4* v4 = (const float4*)(values + (size_t)t * EE);

    // angles = W_ang @ v + b_ang
    float ang[16];
#pragma unroll
    for (int p = 0; p < 16; p++) ang[p] = sb[p];
#pragma unroll
    for (int eg = 0; eg < 16; eg++) {
        float4 v = v4[eg];
#pragma unroll
        for (int p = 0; p < 16; p++) {
            const float* w = &sW[p * 64 + eg * 4];
            ang[p] += w[0] * v.x + w[1] * v.y + w[2] * v.z + w[3] * v.w;
        }
    }

    // |0000>
    float ar[16], ai[16];
#pragma unroll
    for (int i = 0; i < 16; i++) { ar[i] = 0.f; ai[i] = 0.f; }
    ar[0] = 1.0f;

    // Ansatz 14, 1 layer
    apply_ry<0>(ar, ai, ang[0]);
    apply_ry<1>(ar, ai, ang[1]);
    apply_ry<2>(ar, ai, ang[2]);
    apply_ry<3>(ar, ai, ang[3]);
    apply_crx<3, 0>(ar, ai, ang[4]);
    apply_crx<2, 3>(ar, ai, ang[5]);
    apply_crx<1, 2>(ar, ai, ang[6]);
    apply_crx<0, 1>(ar, ai, ang[7]);
    apply_ry<0>(ar, ai, ang[8]);
    apply_ry<1>(ar, ai, ang[9]);
    apply_ry<2>(ar, ai, ang[10]);
    apply_ry<3>(ar, ai, ang[11]);
    apply_crx<3, 2>(ar, ai, ang[12]);
    apply_crx<0, 3>(ar, ai, ang[13]);
    apply_crx<1, 0>(ar, ai, ang[14]);
    apply_crx<2, 1>(ar, ai, ang[15]);

    float meas[12];
    measure_xyz_w<0>(ar, ai, meas);
    measure_xyz_w<1>(ar, ai, meas);
    measure_xyz_w<2>(ar, ai, meas);
    measure_xyz_w<3>(ar, ai, meas);

    // qev = meas @ W_out^T + b_out  (W_out is [E, 12] row-major)
    float4* o4 = (float4*)(g_qev + (size_t)t * EE);
#pragma unroll
    for (int eg = 0; eg < 16; eg++) {
        float r[4];
#pragma unroll
        for (int q = 0; q < 4; q++) {
            int e = eg * 4 + q;
            float acc = sbo[e];
            const float* w = &sWo[e * 12];
#pragma unroll
            for (int mm = 0; mm < 12; mm++) acc += meas[mm] * w[mm];
            r[q] = acc;
        }
        o4[eg] = make_float4(r[0], r[1], r[2], r[3]);
    }
}

// ---------------------------------------------------------------------------
// Kernel 2: causal flash attention, fp32, 64x64 tiles, 4x4 register fragments
// ---------------------------------------------------------------------------
#define BM 64
#define BN 64
#define PAD 68
#define SMEM_FLOATS (4 * 64 * PAD)
#define SMEM_BYTES (SMEM_FLOATS * 4)

__global__ __launch_bounds__(256) void attn_kernel(
    const float* __restrict__ Q, const float* __restrict__ K,
    float* __restrict__ Out) {
    extern __shared__ float sm[];
    float* Qs = sm;                 // [e][r], stride PAD (transposed)
    float* Ks = sm + 64 * PAD;      // [e][j], stride PAD (transposed)
    float* Vs = sm + 2 * 64 * PAD;  // [j][d], stride PAD
    float* Ps = sm + 3 * 64 * PAD;  // [j][r], stride PAD (transposed P)

    const int bh = blockIdx.y;          // b*H + h
    const int b = bh >> 3, h = bh & 7;
    const int qb = (gridDim.x - 1) - blockIdx.x;  // big blocks first
    const int qbase = qb * BM;
    const int tid = threadIdx.x;
    const int tx = tid & 15, ty = tid >> 4;
    const int r0 = ty * 4, c0 = tx * 4;

    const size_t rowstride = (size_t)HH * EE;                 // 512
    const size_t base = (size_t)b * SS * rowstride + (size_t)h * EE;

    // Load Q tile transposed: Qs[e][r]
    for (int task = tid; task < 1024; task += 256) {
        int j = task >> 4, eg = task & 15;
        float4 v = *(const float4*)(Q + base + (size_t)(qbase + j) * rowstride + eg * 4);
        Qs[(eg * 4 + 0) * PAD + j] = v.x;
        Qs[(eg * 4 + 1) * PAD + j] = v.y;
        Qs[(eg * 4 + 2) * PAD + j] = v.z;
        Qs[(eg * 4 + 3) * PAD + j] = v.w;
    }

    float o[4][4];
    float m[4], l[4];
#pragma unroll
    for (int i = 0; i < 4; i++) {
        m[i] = -1e30f; l[i] = 0.f;
#pragma unroll
        for (int j = 0; j < 4; j++) o[i][j] = 0.f;
    }

    const float scale = 0.125f;   // 1/sqrt(64)

    for (int kb = 0; kb <= qb; kb++) {
        const int kbase = kb * BN;
        __syncthreads();  // protect Ks/Vs/Ps from previous iteration readers
        for (int task = tid; task < 1024; task += 256) {
            int j = task >> 4, eg = task & 15;
            size_t g = base + (size_t)(kbase + j) * rowstride + eg * 4;
            float4 kv = *(const float4*)(K + g);
            Ks[(eg * 4 + 0) * PAD + j] = kv.x;
            Ks[(eg * 4 + 1) * PAD + j] = kv.y;
            Ks[(eg * 4 + 2) * PAD + j] = kv.z;
            Ks[(eg * 4 + 3) * PAD + j] = kv.w;
            float4 vv = *(const float4*)(g_qev + g);
            *(float4*)(Vs + j * PAD + eg * 4) = vv;
        }
        __syncthreads();

        // S = Q K^T (4x4 fragment per thread)
        float s[4][4];
#pragma unroll
        for (int i = 0; i < 4; i++)
#pragma unroll
            for (int j = 0; j < 4; j++) s[i][j] = 0.f;

#pragma unroll 8
        for (int e = 0; e < 64; e++) {
            float4 qv = *(const float4*)(Qs + e * PAD + r0);
            float4 kv = *(const float4*)(Ks + e * PAD + c0);
            s[0][0] += qv.x * kv.x; s[0][1] += qv.x * kv.y; s[0][2] += qv.x * kv.z; s[0][3] += qv.x * kv.w;
            s[1][0] += qv.y * kv.x; s[1][1] += qv.y * kv.y; s[1][2] += qv.y * kv.z; s[1][3] += qv.y * kv.w;
            s[2][0] += qv.z * kv.x; s[2][1] += qv.z * kv.y; s[2][2] += qv.z * kv.z; s[2][3] += qv.z * kv.w;
            s[3][0] += qv.w * kv.x; s[3][1] += qv.w * kv.y; s[3][2] += qv.w * kv.z; s[3][3] += qv.w * kv.w;
        }

        // scale + causal mask (mask only possible on the diagonal tile)
        if (kb == qb) {
#pragma unroll
            for (int i = 0; i < 4; i++)
#pragma unroll
                for (int j = 0; j < 4; j++) {
                    float v = s[i][j] * scale;
                    if (kbase + c0 + j > qbase + r0 + i) v = -1e9f;
                    s[i][j] = v;
                }
        } else {
#pragma unroll
            for (int i = 0; i < 4; i++)
#pragma unroll
                for (int j = 0; j < 4; j++) s[i][j] *= scale;
        }

        // online softmax per row (rows split over 16 tx lanes within warp)
#pragma unroll
        for (int i = 0; i < 4; i++) {
            float rm = fmaxf(fmaxf(s[i][0], s[i][1]), fmaxf(s[i][2], s[i][3]));
#pragma unroll
            for (int off = 8; off > 0; off >>= 1)
                rm = fmaxf(rm, __shfl_xor_sync(0xffffffffu, rm, off));
            float mnew = fmaxf(m[i], rm);
            float alpha = __expf(m[i] - mnew);
            m[i] = mnew;
            float rs = 0.f;
#pragma unroll
            for (int j = 0; j < 4; j++) {
                float p = __expf(s[i][j] - mnew);
                s[i][j] = p;
                rs += p;
            }
#pragma unroll
            for (int off = 8; off > 0; off >>= 1)
                rs += __shfl_xor_sync(0xffffffffu, rs, off);
            l[i] = l[i] * alpha + rs;
#pragma unroll
            for (int j = 0; j < 4; j++) o[i][j] *= alpha;
        }

        // write P transposed: Ps[col][row]
#pragma unroll
        for (int j = 0; j < 4; j++) {
            *(float4*)(Ps + (c0 + j) * PAD + r0) =
                make_float4(s[0][j], s[1][j], s[2][j], s[3][j]);
        }
        __syncthreads();

        // O += P V
#pragma unroll 8
        for (int j = 0; j < 64; j++) {
            float4 pv = *(const float4*)(Ps + j * PAD + r0);
            float4 vv = *(const float4*)(Vs + j * PAD + c0);
            o[0][0] += pv.x * vv.x; o[0][1] += pv.x * vv.y; o[0][2] += pv.x * vv.z; o[0][3] += pv.x * vv.w;
            o[1][0] += pv.y * vv.x; o[1][1] += pv.y * vv.y; o[1][2] += pv.y * vv.z; o[1][3] += pv.y * vv.w;
            o[2][0] += pv.z * vv.x; o[2][1] += pv.z * vv.y; o[2][2] += pv.z * vv.z; o[2][3] += pv.z * vv.w;
            o[3][0] += pv.w * vv.x; o[3][1] += pv.w * vv.y; o[3][2] += pv.w * vv.z; o[3][3] += pv.w * vv.w;
        }
    }

    // normalize + store [B,L,H,E] fp32
#pragma unroll
    for (int i = 0; i < 4; i++) {
        float inv = 1.0f / l[i];
        *(float4*)(Out + base + (size_t)(qbase + r0 + i) * rowstride + c0) =
            make_float4(o[i][0] * inv, o[i][1] * inv, o[i][2] * inv, o[i][3] * inv);
    }
}

// ---------------------------------------------------------------------------
extern "C" void kernel_launch(void* const* d_in, const int* in_sizes, int n_in,
                              void* d_out, int out_size) {
    const float* Q  = (const float*)d_in[0];
    const float* K  = (const float*)d_in[1];
    const float* V  = (const float*)d_in[2];
    const float* Wa = (const float*)d_in[3];
    const float* ba = (const float*)d_in[4];
    const float* Wo = (const float*)d_in[5];
    const float* bo = (const float*)d_in[6];
    float* Out = (float*)d_out;

    cudaFuncSetAttribute(attn_kernel, cudaFuncAttributeMaxDynamicSharedMemorySize,
                         SMEM_BYTES);

    quantum_kernel<<<NTOK / 256, 256>>>(V, Wa, ba, Wo, bo);

    dim3 grid(LL / BM, BB * HH);
    attn_kernel<<<grid, 256, SMEM_BYTES>>>(Q, K, Out);
}

// round 2
// speedup vs baseline: 1.7367x; 1.7367x over previous
#include <cuda_runtime.h>
#include <cuda_bf16.h>
#include <cstdint>
#include <math.h>

// Problem constants
#define BB 2
#define LL 2048
#define SS 2048
#define HH 8
#define EE 64
#define NTOK (BB * SS * HH)          // 32768

// qev buffer: quantum-encoded values, layout identical to values [B,S,H,E]
__device__ float g_qev[(size_t)NTOK * EE];

// ---------------------------------------------------------------------------
// Quantum circuit helpers (4 qubits, 16 complex amplitudes, wire 0 = MSB)
// ---------------------------------------------------------------------------
template <int W>
__device__ __forceinline__ void apply_ry(float* ar, float* ai, float th) {
    float s, c;
    __sincosf(th * 0.5f, &s, &c);
    const int mask = 8 >> W;
#pragma unroll
    for (int i = 0; i < 16; i++) {
        if ((i & mask) == 0) {
            const int j = i | mask;
            float r0 = ar[i], i0 = ai[i], r1 = ar[j], i1 = ai[j];
            ar[i] = c * r0 - s * r1;  ai[i] = c * i0 - s * i1;
            ar[j] = s * r0 + c * r1;  ai[j] = s * i0 + c * i1;
        }
    }
}

template <int C, int T>
__device__ __forceinline__ void apply_crx(float* ar, float* ai, float th) {
    float s, c;
    __sincosf(th * 0.5f, &s, &c);
    const int cm = 8 >> C, tm = 8 >> T;
#pragma unroll
    for (int i = 0; i < 16; i++) {
        if ((i & cm) != 0 && (i & tm) == 0) {
            const int j = i | tm;
            float r0 = ar[i], i0 = ai[i], r1 = ar[j], i1 = ai[j];
            ar[i] = c * r0 + s * i1;  ai[i] = c * i0 - s * r1;
            ar[j] = c * r1 + s * i0;  ai[j] = c * i1 - s * r0;
        }
    }
}

template <int W>
__device__ __forceinline__ void measure_xyz_w(const float* ar, const float* ai,
                                              float* meas) {
    const int mask = 8 >> W;
    float pr = 0.f, pi = 0.f, z = 0.f;
#pragma unroll
    for (int i = 0; i < 16; i++) {
        if ((i & mask) == 0) {
            const int j = i | mask;
            pr += ar[i] * ar[j] + ai[i] * ai[j];
            pi += ar[i] * ai[j] - ai[i] * ar[j];
            z  += ar[i] * ar[i] + ai[i] * ai[i]
                - ar[j] * ar[j] - ai[j] * ai[j];
        }
    }
    meas[W]     = 2.0f * pr;
    meas[4 + W] = 2.0f * pi;
    meas[8 + W] = z;
}

// ---------------------------------------------------------------------------
// Kernel 1: values -> angles -> PQC -> Pauli expvals -> qev  (one thread/token)
// ---------------------------------------------------------------------------
__global__ __launch_bounds__(256) void quantum_kernel(
    const float* __restrict__ values, const float* __restrict__ W_ang,
    const float* __restrict__ b_ang, const float* __restrict__ W_out,
    const float* __restrict__ b_out) {
    __shared__ float sW[16 * 64];
    __shared__ float sb[16];
    __shared__ float sWo[64 * 12];
    __shared__ float sbo[64];
    int tid = threadIdx.x;
    for (int i = tid; i < 16 * 64; i += 256) sW[i] = W_ang[i];
    for (int i = tid; i < 64 * 12; i += 256) sWo[i] = W_out[i];
    if (tid < 16) sb[tid] = b_ang[tid];
    if (tid < 64) sbo[tid] = b_out[tid];
    __syncthreads();

    int t = blockIdx.x * 256 + tid;
    const float4* v4 = (const float4*)(values + (size_t)t * EE);

    float ang[16];
#pragma unroll
    for (int p = 0; p < 16; p++) ang[p] = sb[p];
#pragma unroll
    for (int eg = 0; eg < 16; eg++) {
        float4 v = v4[eg];
#pragma unroll
        for (int p = 0; p < 16; p++) {
            const float* w = &sW[p * 64 + eg * 4];
            ang[p] += w[0] * v.x + w[1] * v.y + w[2] * v.z + w[3] * v.w;
        }
    }

    float ar[16], ai[16];
#pragma unroll
    for (int i = 0; i < 16; i++) { ar[i] = 0.f; ai[i] = 0.f; }
    ar[0] = 1.0f;

    apply_ry<0>(ar, ai, ang[0]);
    apply_ry<1>(ar, ai, ang[1]);
    apply_ry<2>(ar, ai, ang[2]);
    apply_ry<3>(ar, ai, ang[3]);
    apply_crx<3, 0>(ar, ai, ang[4]);
    apply_crx<2, 3>(ar, ai, ang[5]);
    apply_crx<1, 2>(ar, ai, ang[6]);
    apply_crx<0, 1>(ar, ai, ang[7]);
    apply_ry<0>(ar, ai, ang[8]);
    apply_ry<1>(ar, ai, ang[9]);
    apply_ry<2>(ar, ai, ang[10]);
    apply_ry<3>(ar, ai, ang[11]);
    apply_crx<3, 2>(ar, ai, ang[12]);
    apply_crx<0, 3>(ar, ai, ang[13]);
    apply_crx<1, 0>(ar, ai, ang[14]);
    apply_crx<2, 1>(ar, ai, ang[15]);

    float meas[12];
    measure_xyz_w<0>(ar, ai, meas);
    measure_xyz_w<1>(ar, ai, meas);
    measure_xyz_w<2>(ar, ai, meas);
    measure_xyz_w<3>(ar, ai, meas);

    float4* o4 = (float4*)(g_qev + (size_t)t * EE);
#pragma unroll
    for (int eg = 0; eg < 16; eg++) {
        float r[4];
#pragma unroll
        for (int q = 0; q < 4; q++) {
            int e = eg * 4 + q;
            float acc = sbo[e];
            const float* w = &sWo[e * 12];
#pragma unroll
            for (int mm = 0; mm < 12; mm++) acc += meas[mm] * w[mm];
            r[q] = acc;
        }
        o4[eg] = make_float4(r[0], r[1], r[2], r[3]);
    }
}

// ---------------------------------------------------------------------------
// Kernel 2: causal flash attention on tensor cores (tf32 mma.sync m16n8k8)
// BM=128 rows/CTA, 8 warps * 16 rows each, BN=64 keys/iter, E=64.
// ---------------------------------------------------------------------------
#define BM 128
#define BN 64
#define QS_STR 68   // stride % 32 == 4 -> A-frag (8 rows x 4 cols) conflict-free
#define KS_STR 72   // stride % 32 == 8 -> B-frag (4 rows x 8 cols) conflict-free
#define VS_STR 72
#define PS_STR 68
#define SM_WORDS (BM * QS_STR + BN * KS_STR + BN * VS_STR + BM * PS_STR)
#define SMEM_BYTES (SM_WORDS * 4)

__device__ __forceinline__ uint32_t f2tf(float x) {
    uint32_t r;
    asm("cvt.rna.tf32.f32 %0, %1;" : "=r"(r) : "f"(x));
    return r;
}

__device__ __forceinline__ void mma8(float* d, const uint32_t* a, const uint32_t* b) {
    asm volatile(
        "mma.sync.aligned.m16n8k8.row.col.f32.tf32.tf32.f32 "
        "{%0,%1,%2,%3}, {%4,%5,%6,%7}, {%8,%9}, {%0,%1,%2,%3};"
        : "+f"(d[0]), "+f"(d[1]), "+f"(d[2]), "+f"(d[3])
        : "r"(a[0]), "r"(a[1]), "r"(a[2]), "r"(a[3]), "r"(b[0]), "r"(b[1]));
}

__global__ __launch_bounds__(256) void attn_kernel(
    const float* __restrict__ Q, const float* __restrict__ K,
    float* __restrict__ Out) {
    extern __shared__ uint32_t sm[];
    uint32_t* Qs = sm;                    // [qrow][e]   tf32
    uint32_t* Ks = Qs + BM * QS_STR;      // [e][key]    tf32 (transposed)
    uint32_t* Vs = Ks + BN * KS_STR;      // [key][e]    tf32
    uint32_t* Ps = Vs + BN * VS_STR;      // [qrow][key] tf32

    const int bh = blockIdx.y;
    const int b = bh >> 3, h = bh & 7;
    const int qb = (gridDim.x - 1) - blockIdx.x;   // big blocks first
    const int qbase = qb * BM;
    const int tid = threadIdx.x;
    const int wid = tid >> 5, lane = tid & 31;
    const int g = lane >> 2, t = lane & 3;         // groupID, threadID_in_group
    const int R0 = wid * 16;                        // warp's first q-row in tile

    const size_t rs = (size_t)HH * EE;             // 512
    const size_t base = (size_t)b * SS * rs + (size_t)h * EE;

    // Load Q tile [128][64] -> tf32, natural layout
    for (int task = tid; task < BM * 16; task += 256) {
        int row = task >> 4, eg = task & 15;
        float4 v = *(const float4*)(Q + base + (size_t)(qbase + row) * rs + eg * 4);
        uint32_t* dst = Qs + row * QS_STR + eg * 4;
        dst[0] = f2tf(v.x); dst[1] = f2tf(v.y);
        dst[2] = f2tf(v.z); dst[3] = f2tf(v.w);
    }

    float o[8][4];
#pragma unroll
    for (int nt = 0; nt < 8; nt++)
#pragma unroll
        for (int j = 0; j < 4; j++) o[nt][j] = 0.f;
    float m0 = -1e30f, m1 = -1e30f, l0 = 0.f, l1 = 0.f;
    const float scale = 0.125f;   // 1/sqrt(64)

    const int kb_end = 2 * qb + 1;
    for (int kb = 0; kb <= kb_end; kb++) {
        const int kbase = kb * BN;
        __syncthreads();
        // K tile transposed -> Ks[e][key] (key fast-varying lane -> conflict-free STS)
        for (int task = tid; task < 1024; task += 256) {
            int j = task & 63, eg = task >> 6;   // eg: 0..15 over 4 passes
            float4 kv = *(const float4*)(K + base + (size_t)(kbase + j) * rs + eg * 4);
            Ks[(eg * 4 + 0) * KS_STR + j] = f2tf(kv.x);
            Ks[(eg * 4 + 1) * KS_STR + j] = f2tf(kv.y);
            Ks[(eg * 4 + 2) * KS_STR + j] = f2tf(kv.z);
            Ks[(eg * 4 + 3) * KS_STR + j] = f2tf(kv.w);
        }
        // V tile natural -> Vs[key][e]
        for (int task = tid; task < 1024; task += 256) {
            int j = task >> 4, eg = task & 15;
            float4 vv = *(const float4*)(g_qev + base + (size_t)(kbase + j) * rs + eg * 4);
            uint32_t* dst = Vs + j * VS_STR + eg * 4;
            dst[0] = f2tf(vv.x); dst[1] = f2tf(vv.y);
            dst[2] = f2tf(vv.z); dst[3] = f2tf(vv.w);
        }
        __syncthreads();

        // ---- S = Q K^T : warp computes 16x64 via 8 ksteps x 8 ntiles ----
        float s[8][4];
#pragma unroll
        for (int nt = 0; nt < 8; nt++)
#pragma unroll
            for (int j = 0; j < 4; j++) s[nt][j] = 0.f;

#pragma unroll
        for (int ks = 0; ks < 8; ks++) {
            uint32_t a[4];
            const int c = ks * 8 + t;
            a[0] = Qs[(R0 + g) * QS_STR + c];
            a[1] = Qs[(R0 + g + 8) * QS_STR + c];
            a[2] = Qs[(R0 + g) * QS_STR + c + 4];
            a[3] = Qs[(R0 + g + 8) * QS_STR + c + 4];
#pragma unroll
            for (int nt = 0; nt < 8; nt++) {
                uint32_t bf[2];
                bf[0] = Ks[(ks * 8 + t) * KS_STR + nt * 8 + g];
                bf[1] = Ks[(ks * 8 + t + 4) * KS_STR + nt * 8 + g];
                mma8(s[nt], a, bf);
            }
        }

        // ---- scale + causal mask (only last two k-iterations can mask) ----
        if (kb >= 2 * qb) {
            const int row0 = qbase + R0 + g, row1 = row0 + 8;
#pragma unroll
            for (int nt = 0; nt < 8; nt++) {
                int c0 = kbase + nt * 8 + 2 * t, c1 = c0 + 1;
                s[nt][0] = (c0 > row0) ? -1e9f : s[nt][0] * scale;
                s[nt][1] = (c1 > row0) ? -1e9f : s[nt][1] * scale;
                s[nt][2] = (c0 > row1) ? -1e9f : s[nt][2] * scale;
                s[nt][3] = (c1 > row1) ? -1e9f : s[nt][3] * scale;
            }
        } else {
#pragma unroll
            for (int nt = 0; nt < 8; nt++)
#pragma unroll
                for (int j = 0; j < 4; j++) s[nt][j] *= scale;
        }

        // ---- online softmax: rows (R0+g) and (R0+g+8), cols across 4 t-lanes ----
        float rm0 = -1e30f, rm1 = -1e30f;
#pragma unroll
        for (int nt = 0; nt < 8; nt++) {
            rm0 = fmaxf(rm0, fmaxf(s[nt][0], s[nt][1]));
            rm1 = fmaxf(rm1, fmaxf(s[nt][2], s[nt][3]));
        }
        rm0 = fmaxf(rm0, __shfl_xor_sync(0xffffffffu, rm0, 1));
        rm0 = fmaxf(rm0, __shfl_xor_sync(0xffffffffu, rm0, 2));
        rm1 = fmaxf(rm1, __shfl_xor_sync(0xffffffffu, rm1, 1));
        rm1 = fmaxf(rm1, __shfl_xor_sync(0xffffffffu, rm1, 2));

        float mn0 = fmaxf(m0, rm0), mn1 = fmaxf(m1, rm1);
        float al0 = __expf(m0 - mn0), al1 = __expf(m1 - mn1);
        m0 = mn0; m1 = mn1;
        float rs0 = 0.f, rs1 = 0.f;
#pragma unroll
        for (int nt = 0; nt < 8; nt++) {
            s[nt][0] = __expf(s[nt][0] - mn0);
            s[nt][1] = __expf(s[nt][1] - mn0);
            s[nt][2] = __expf(s[nt][2] - mn1);
            s[nt][3] = __expf(s[nt][3] - mn1);
            rs0 += s[nt][0] + s[nt][1];
            rs1 += s[nt][2] + s[nt][3];
        }
        rs0 += __shfl_xor_sync(0xffffffffu, rs0, 1);
        rs0 += __shfl_xor_sync(0xffffffffu, rs0, 2);
        rs1 += __shfl_xor_sync(0xffffffffu, rs1, 1);
        rs1 += __shfl_xor_sync(0xffffffffu, rs1, 2);
        l0 = l0 * al0 + rs0;
        l1 = l1 * al1 + rs1;
#pragma unroll
        for (int nt = 0; nt < 8; nt++) {
            o[nt][0] *= al0; o[nt][1] *= al0;
            o[nt][2] *= al1; o[nt][3] *= al1;
        }

        // ---- P -> smem (warp-private rows), rearrange D-frag to A-frag ----
#pragma unroll
        for (int nt = 0; nt < 8; nt++) {
            const int cc = nt * 8 + 2 * t;
            *(uint2*)(Ps + (R0 + g) * PS_STR + cc) =
                make_uint2(f2tf(s[nt][0]), f2tf(s[nt][1]));
            *(uint2*)(Ps + (R0 + g + 8) * PS_STR + cc) =
                make_uint2(f2tf(s[nt][2]), f2tf(s[nt][3]));
        }
        __syncwarp();

        // ---- O += P V ----
#pragma unroll
        for (int ks = 0; ks < 8; ks++) {
            uint32_t a[4];
            const int c = ks * 8 + t;
            a[0] = Ps[(R0 + g) * PS_STR + c];
            a[1] = Ps[(R0 + g + 8) * PS_STR + c];
            a[2] = Ps[(R0 + g) * PS_STR + c + 4];
            a[3] = Ps[(R0 + g + 8) * PS_STR + c + 4];
#pragma unroll
            for (int nt = 0; nt < 8; nt++) {
                uint32_t bf[2];
                bf[0] = Vs[(ks * 8 + t) * VS_STR + nt * 8 + g];
                bf[1] = Vs[(ks * 8 + t + 4) * VS_STR + nt * 8 + g];
                mma8(o[nt], a, bf);
            }
        }
    }

    // ---- normalize + store [B,L,H,E] fp32 ----
    const float i0 = 1.0f / l0, i1 = 1.0f / l1;
    const size_t out0 = base + (size_t)(qbase + R0 + g) * rs;
    const size_t out1 = base + (size_t)(qbase + R0 + g + 8) * rs;
#pragma unroll
    for (int nt = 0; nt < 8; nt++) {
        const int cc = nt * 8 + 2 * t;
        *(float2*)(Out + out0 + cc) = make_float2(o[nt][0] * i0, o[nt][1] * i0);
        *(float2*)(Out + out1 + cc) = make_float2(o[nt][2] * i1, o[nt][3] * i1);
    }
}

// ---------------------------------------------------------------------------
extern "C" void kernel_launch(void* const* d_in, const int* in_sizes, int n_in,
                              void* d_out, int out_size) {
    const float* Q  = (const float*)d_in[0];
    const float* K  = (const float*)d_in[1];
    const float* V  = (const float*)d_in[2];
    const float* Wa = (const float*)d_in[3];
    const float* ba = (const float*)d_in[4];
    const float* Wo = (const float*)d_in[5];
    const float* bo = (const float*)d_in[6];
    float* Out = (float*)d_out;

    cudaFuncSetAttribute(attn_kernel, cudaFuncAttributeMaxDynamicSharedMemorySize,
                         SMEM_BYTES);

    quantum_kernel<<<NTOK / 256, 256>>>(V, Wa, ba, Wo, bo);

    dim3 grid(LL / BM, BB * HH);
    attn_kernel<<<grid, 256, SMEM_BYTES>>>(Q, K, Out);
}

// round 3
// speedup vs baseline: 3.9089x; 2.2507x over previous
#include <cuda_runtime.h>
#include <cuda_bf16.h>
#include <cstdint>
#include <math.h>

// Problem constants
#define BB 2
#define LL 2048
#define SS 2048
#define HH 8
#define EE 64
#define NTOK (BB * SS * HH)          // 32768

__device__ float g_qev[(size_t)NTOK * EE];
__device__ int g_ctr;

// ---------------------------------------------------------------------------
// Quantum circuit helpers (4 qubits, 16 complex amplitudes, wire 0 = MSB)
// ---------------------------------------------------------------------------
template <int W>
__device__ __forceinline__ void apply_ry(float* ar, float* ai, float th) {
    float s, c;
    __sincosf(th * 0.5f, &s, &c);
    const int mask = 8 >> W;
#pragma unroll
    for (int i = 0; i < 16; i++) {
        if ((i & mask) == 0) {
            const int j = i | mask;
            float r0 = ar[i], i0 = ai[i], r1 = ar[j], i1 = ai[j];
            ar[i] = c * r0 - s * r1;  ai[i] = c * i0 - s * i1;
            ar[j] = s * r0 + c * r1;  ai[j] = s * i0 + c * i1;
        }
    }
}

template <int C, int T>
__device__ __forceinline__ void apply_crx(float* ar, float* ai, float th) {
    float s, c;
    __sincosf(th * 0.5f, &s, &c);
    const int cm = 8 >> C, tm = 8 >> T;
#pragma unroll
    for (int i = 0; i < 16; i++) {
        if ((i & cm) != 0 && (i & tm) == 0) {
            const int j = i | tm;
            float r0 = ar[i], i0 = ai[i], r1 = ar[j], i1 = ai[j];
            ar[i] = c * r0 + s * i1;  ai[i] = c * i0 - s * r1;
            ar[j] = c * r1 + s * i0;  ai[j] = c * i1 - s * r0;
        }
    }
}

template <int W>
__device__ __forceinline__ void measure_xyz_w(const float* ar, const float* ai,
                                              float* meas) {
    const int mask = 8 >> W;
    float pr = 0.f, pi = 0.f, z = 0.f;
#pragma unroll
    for (int i = 0; i < 16; i++) {
        if ((i & mask) == 0) {
            const int j = i | mask;
            pr += ar[i] * ar[j] + ai[i] * ai[j];
            pi += ar[i] * ai[j] - ai[i] * ar[j];
            z  += ar[i] * ar[i] + ai[i] * ai[i]
                - ar[j] * ar[j] - ai[j] * ai[j];
        }
    }
    meas[W]     = 2.0f * pr;
    meas[4 + W] = 2.0f * pi;
    meas[8 + W] = z;
}

// ---------------------------------------------------------------------------
// Kernel 1: values -> angles -> PQC -> Pauli expvals -> qev (one thread/token)
// ---------------------------------------------------------------------------
__global__ __launch_bounds__(256) void quantum_kernel(
    const float* __restrict__ values, const float* __restrict__ W_ang,
    const float* __restrict__ b_ang, const float* __restrict__ W_out,
    const float* __restrict__ b_out) {
    __shared__ float sW[16 * 64];
    __shared__ float sb[16];
    __shared__ float sWo[64 * 12];
    __shared__ float sbo[64];
    int tid = threadIdx.x;
    if (blockIdx.x == 0 && tid == 0) g_ctr = 0;   // reset attn work queue
    for (int i = tid; i < 16 * 64; i += 256) sW[i] = W_ang[i];
    for (int i = tid; i < 64 * 12; i += 256) sWo[i] = W_out[i];
    if (tid < 16) sb[tid] = b_ang[tid];
    if (tid < 64) sbo[tid] = b_out[tid];
    __syncthreads();

    int t = blockIdx.x * 256 + tid;
    const float4* v4 = (const float4*)(values + (size_t)t * EE);

    float ang[16];
#pragma unroll
    for (int p = 0; p < 16; p++) ang[p] = sb[p];
#pragma unroll
    for (int eg = 0; eg < 16; eg++) {
        float4 v = v4[eg];
#pragma unroll
        for (int p = 0; p < 16; p++) {
            const float* w = &sW[p * 64 + eg * 4];
            ang[p] += w[0] * v.x + w[1] * v.y + w[2] * v.z + w[3] * v.w;
        }
    }

    float ar[16], ai[16];
#pragma unroll
    for (int i = 0; i < 16; i++) { ar[i] = 0.f; ai[i] = 0.f; }
    ar[0] = 1.0f;

    apply_ry<0>(ar, ai, ang[0]);
    apply_ry<1>(ar, ai, ang[1]);
    apply_ry<2>(ar, ai, ang[2]);
    apply_ry<3>(ar, ai, ang[3]);
    apply_crx<3, 0>(ar, ai, ang[4]);
    apply_crx<2, 3>(ar, ai, ang[5]);
    apply_crx<1, 2>(ar, ai, ang[6]);
    apply_crx<0, 1>(ar, ai, ang[7]);
    apply_ry<0>(ar, ai, ang[8]);
    apply_ry<1>(ar, ai, ang[9]);
    apply_ry<2>(ar, ai, ang[10]);
    apply_ry<3>(ar, ai, ang[11]);
    apply_crx<3, 2>(ar, ai, ang[12]);
    apply_crx<0, 3>(ar, ai, ang[13]);
    apply_crx<1, 0>(ar, ai, ang[14]);
    apply_crx<2, 1>(ar, ai, ang[15]);

    float meas[12];
    measure_xyz_w<0>(ar, ai, meas);
    measure_xyz_w<1>(ar, ai, meas);
    measure_xyz_w<2>(ar, ai, meas);
    measure_xyz_w<3>(ar, ai, meas);

    float4* o4 = (float4*)(g_qev + (size_t)t * EE);
#pragma unroll
    for (int eg = 0; eg < 16; eg++) {
        float r[4];
#pragma unroll
        for (int q = 0; q < 4; q++) {
            int e = eg * 4 + q;
            float acc = sbo[e];
            const float* w = &sWo[e * 12];
#pragma unroll
            for (int mm = 0; mm < 12; mm++) acc += meas[mm] * w[mm];
            r[q] = acc;
        }
        o4[eg] = make_float4(r[0], r[1], r[2], r[3]);
    }
}

// ---------------------------------------------------------------------------
// Kernel 2: persistent causal flash attention, tf32 mma, cp.async pipeline
// BM=128 rows/item, 8 warps * 16 rows, BN=64 keys/iter, E=64, raw-fp32->tf32
// ---------------------------------------------------------------------------
#define BM 128
#define BN 64
#define QS_STR 68   // [row][e]  : A-frag banks (4g+t) distinct
#define KS_STR 68   // [key][e]  : QK B-frag banks (4g+t) distinct
#define VS_STR 72   // [key][e]  : PV B-frag banks (8t+g) distinct
#define PS_STR 68   // [row][key]: A-frag
#define N_ITEMS 256
#define SM_WORDS (BM * QS_STR + BM * PS_STR + 2 * BN * KS_STR + 2 * BN * VS_STR)
#define SMEM_BYTES (SM_WORDS * 4)

__device__ __forceinline__ void mma8(float* d, const uint32_t* a, const uint32_t* b) {
    asm volatile(
        "mma.sync.aligned.m16n8k8.row.col.f32.tf32.tf32.f32 "
        "{%0,%1,%2,%3}, {%4,%5,%6,%7}, {%8,%9}, {%0,%1,%2,%3};"
        : "+f"(d[0]), "+f"(d[1]), "+f"(d[2]), "+f"(d[3])
        : "r"(a[0]), "r"(a[1]), "r"(a[2]), "r"(a[3]), "r"(b[0]), "r"(b[1]));
}

__device__ __forceinline__ void cp16(uint32_t saddr, const void* g) {
    asm volatile("cp.async.cg.shared.global [%0], [%1], 16;"
                 :: "r"(saddr), "l"(g));
}
__device__ __forceinline__ void cp_commit() {
    asm volatile("cp.async.commit_group;");
}
__device__ __forceinline__ void cp_wait0() {
    asm volatile("cp.async.wait_group 0;");
}

__global__ __launch_bounds__(256, 1) void attn_kernel(
    const float* __restrict__ Q, const float* __restrict__ K,
    float* __restrict__ Out) {
    extern __shared__ uint32_t sm[];
    uint32_t* Qs = sm;                                 // [row][e]
    uint32_t* Ps = Qs + BM * QS_STR;                   // [row][key]
    uint32_t* Ks0 = Ps + BM * PS_STR;                  // double-buffered
    uint32_t* Vs0 = Ks0 + 2 * BN * KS_STR;
    __shared__ int sItem;

    const int tid = threadIdx.x;
    const int wid = tid >> 5, lane = tid & 31;
    const int g = lane >> 2, t = lane & 3;
    const int R0 = wid * 16;
    const size_t rs = (size_t)HH * EE;                 // 512
    const float scale = 0.125f;

    const uint32_t sQ = (uint32_t)__cvta_generic_to_shared(Qs);
    const uint32_t sK = (uint32_t)__cvta_generic_to_shared(Ks0);
    const uint32_t sV = (uint32_t)__cvta_generic_to_shared(Vs0);

    for (;;) {
        if (tid == 0) sItem = atomicAdd(&g_ctr, 1);
        __syncthreads();   // broadcast item; also guards smem reuse
        const int item = sItem;
        if (item >= N_ITEMS) break;

        const int bh = item & 15;               // b*H+h
        const int qblk = 15 - (item >> 4);      // big q-blocks first
        const int b = bh >> 3, h = bh & 7;
        const int qbase = qblk * BM;
        const size_t base = (size_t)b * SS * rs + (size_t)h * EE;

        // ---- load Q tile (raw fp32 bits; HMMA.tf32 truncates) ----
        for (int task = tid; task < BM * 16; task += 256) {
            int row = task >> 4, eg = task & 15;
            float4 v = *(const float4*)(Q + base + (size_t)(qbase + row) * rs + eg * 4);
            uint32_t* dst = Qs + row * QS_STR + eg * 4;
            dst[0] = __float_as_uint(v.x); dst[1] = __float_as_uint(v.y);
            dst[2] = __float_as_uint(v.z); dst[3] = __float_as_uint(v.w);
        }

        const int kb_end = 2 * qblk + 1;

        // ---- prologue: async-prefetch tile 0 into buffer 0 ----
        {
            const int kbase = 0;
#pragma unroll
            for (int p = 0; p < 4; p++) {
                int task = tid + 256 * p;
                int row = task >> 4, eg = task & 15;
                const float* gk = K + base + (size_t)(kbase + row) * rs + eg * 4;
                const float* gv = g_qev + base + (size_t)(kbase + row) * rs + eg * 4;
                cp16(sK + (row * KS_STR + eg * 4) * 4, gk);
                cp16(sV + (row * VS_STR + eg * 4) * 4, gv);
            }
            cp_commit();
        }

        float o[8][4];
#pragma unroll
        for (int nt = 0; nt < 8; nt++)
#pragma unroll
            for (int j = 0; j < 4; j++) o[nt][j] = 0.f;
        float m0 = -1e30f, m1 = -1e30f, l0 = 0.f, l1 = 0.f;

        for (int kb = 0; kb <= kb_end; kb++) {
            const int kbase = kb * BN;
            const uint32_t* Kb = Ks0 + (kb & 1) * BN * KS_STR;
            const uint32_t* Vb = Vs0 + (kb & 1) * BN * VS_STR;

            cp_wait0();
            __syncthreads();   // tile kb ready everywhere; prev buffers free

            if (kb < kb_end) {   // prefetch kb+1 into the other buffer
                const int nkbase = kbase + BN;
                const uint32_t oK = sK + ((kb + 1) & 1) * BN * KS_STR * 4;
                const uint32_t oV = sV + ((kb + 1) & 1) * BN * VS_STR * 4;
#pragma unroll
                for (int p = 0; p < 4; p++) {
                    int task = tid + 256 * p;
                    int row = task >> 4, eg = task & 15;
                    const float* gk = K + base + (size_t)(nkbase + row) * rs + eg * 4;
                    const float* gv = g_qev + base + (size_t)(nkbase + row) * rs + eg * 4;
                    cp16(oK + (row * KS_STR + eg * 4) * 4, gk);
                    cp16(oV + (row * VS_STR + eg * 4) * 4, gv);
                }
                cp_commit();
            }

            // ---- S = Q K^T  (B from natural-layout K: B[k=e][n=key]) ----
            float s[8][4];
#pragma unroll
            for (int nt = 0; nt < 8; nt++)
#pragma unroll
                for (int j = 0; j < 4; j++) s[nt][j] = 0.f;

#pragma unroll
            for (int ks = 0; ks < 8; ks++) {
                uint32_t a[4];
                const int c = ks * 8 + t;
                a[0] = Qs[(R0 + g) * QS_STR + c];
                a[1] = Qs[(R0 + g + 8) * QS_STR + c];
                a[2] = Qs[(R0 + g) * QS_STR + c + 4];
                a[3] = Qs[(R0 + g + 8) * QS_STR + c + 4];
#pragma unroll
                for (int nt = 0; nt < 8; nt++) {
                    uint32_t bf[2];
                    const uint32_t* kr = Kb + (nt * 8 + g) * KS_STR + ks * 8;
                    bf[0] = kr[t];
                    bf[1] = kr[t + 4];
                    mma8(s[nt], a, bf);
                }
            }

            // ---- scale + causal mask ----
            if (kb >= 2 * qblk) {
                const int row0 = qbase + R0 + g, row1 = row0 + 8;
#pragma unroll
                for (int nt = 0; nt < 8; nt++) {
                    int c0 = kbase + nt * 8 + 2 * t, c1 = c0 + 1;
                    s[nt][0] = (c0 > row0) ? -1e9f : s[nt][0] * scale;
                    s[nt][1] = (c1 > row0) ? -1e9f : s[nt][1] * scale;
                    s[nt][2] = (c0 > row1) ? -1e9f : s[nt][2] * scale;
                    s[nt][3] = (c1 > row1) ? -1e9f : s[nt][3] * scale;
                }
            } else {
#pragma unroll
                for (int nt = 0; nt < 8; nt++)
#pragma unroll
                    for (int j = 0; j < 4; j++) s[nt][j] *= scale;
            }

            // ---- online softmax ----
            float rm0 = -1e30f, rm1 = -1e30f;
#pragma unroll
            for (int nt = 0; nt < 8; nt++) {
                rm0 = fmaxf(rm0, fmaxf(s[nt][0], s[nt][1]));
                rm1 = fmaxf(rm1, fmaxf(s[nt][2], s[nt][3]));
            }
            rm0 = fmaxf(rm0, __shfl_xor_sync(0xffffffffu, rm0, 1));
            rm0 = fmaxf(rm0, __shfl_xor_sync(0xffffffffu, rm0, 2));
            rm1 = fmaxf(rm1, __shfl_xor_sync(0xffffffffu, rm1, 1));
            rm1 = fmaxf(rm1, __shfl_xor_sync(0xffffffffu, rm1, 2));

            float mn0 = fmaxf(m0, rm0), mn1 = fmaxf(m1, rm1);
            float al0 = __expf(m0 - mn0), al1 = __expf(m1 - mn1);
            m0 = mn0; m1 = mn1;
            float rs0 = 0.f, rs1 = 0.f;
#pragma unroll
            for (int nt = 0; nt < 8; nt++) {
                s[nt][0] = __expf(s[nt][0] - mn0);
                s[nt][1] = __expf(s[nt][1] - mn0);
                s[nt][2] = __expf(s[nt][2] - mn1);
                s[nt][3] = __expf(s[nt][3] - mn1);
                rs0 += s[nt][0] + s[nt][1];
                rs1 += s[nt][2] + s[nt][3];
            }
            rs0 += __shfl_xor_sync(0xffffffffu, rs0, 1);
            rs0 += __shfl_xor_sync(0xffffffffu, rs0, 2);
            rs1 += __shfl_xor_sync(0xffffffffu, rs1, 1);
            rs1 += __shfl_xor_sync(0xffffffffu, rs1, 2);
            l0 = l0 * al0 + rs0;
            l1 = l1 * al1 + rs1;
#pragma unroll
            for (int nt = 0; nt < 8; nt++) {
                o[nt][0] *= al0; o[nt][1] *= al0;
                o[nt][2] *= al1; o[nt][3] *= al1;
            }

            // ---- P -> smem (warp-private rows, raw bits) ----
#pragma unroll
            for (int nt = 0; nt < 8; nt++) {
                const int cc = nt * 8 + 2 * t;
                *(uint2*)(Ps + (R0 + g) * PS_STR + cc) =
                    make_uint2(__float_as_uint(s[nt][0]), __float_as_uint(s[nt][1]));
                *(uint2*)(Ps + (R0 + g + 8) * PS_STR + cc) =
                    make_uint2(__float_as_uint(s[nt][2]), __float_as_uint(s[nt][3]));
            }
            __syncwarp();

            // ---- O += P V  (B from natural-layout V: B[k=key][n=e]) ----
#pragma unroll
            for (int ks = 0; ks < 8; ks++) {
                uint32_t a[4];
                const int c = ks * 8 + t;
                a[0] = Ps[(R0 + g) * PS_STR + c];
                a[1] = Ps[(R0 + g + 8) * PS_STR + c];
                a[2] = Ps[(R0 + g) * PS_STR + c + 4];
                a[3] = Ps[(R0 + g + 8) * PS_STR + c + 4];
#pragma unroll
                for (int nt = 0; nt < 8; nt++) {
                    uint32_t bf[2];
                    bf[0] = Vb[(ks * 8 + t) * VS_STR + nt * 8 + g];
                    bf[1] = Vb[(ks * 8 + t + 4) * VS_STR + nt * 8 + g];
                    mma8(o[nt], a, bf);
                }
            }
        }

        // ---- normalize + store ----
        const float i0 = 1.0f / l0, i1 = 1.0f / l1;
        const size_t out0 = base + (size_t)(qbase + R0 + g) * rs;
        const size_t out1 = base + (size_t)(qbase + R0 + g + 8) * rs;
#pragma unroll
        for (int nt = 0; nt < 8; nt++) {
            const int cc = nt * 8 + 2 * t;
            *(float2*)(Out + out0 + cc) = make_float2(o[nt][0] * i0, o[nt][1] * i0);
            *(float2*)(Out + out1 + cc) = make_float2(o[nt][2] * i1, o[nt][3] * i1);
        }
    }
}

// ---------------------------------------------------------------------------
extern "C" void kernel_launch(void* const* d_in, const int* in_sizes, int n_in,
                              void* d_out, int out_size) {
    const float* Q  = (const float*)d_in[0];
    const float* K  = (const float*)d_in[1];
    const float* V  = (const float*)d_in[2];
    const float* Wa = (const float*)d_in[3];
    const float* ba = (const float*)d_in[4];
    const float* Wo = (const float*)d_in[5];
    const float* bo = (const float*)d_in[6];
    float* Out = (float*)d_out;

    cudaFuncSetAttribute(attn_kernel, cudaFuncAttributeMaxDynamicSharedMemorySize,
                         SMEM_BYTES);

    quantum_kernel<<<NTOK / 256, 256>>>(V, Wa, ba, Wo, bo);
    attn_kernel<<<148, 256, SMEM_BYTES>>>(Q, K, Out);
}

// round 4
// speedup vs baseline: 5.3855x; 1.3777x over previous
#include <cuda_runtime.h>
#include <cuda_fp16.h>
#include <cstdint>
#include <math.h>

// Problem constants
#define BB 2
#define LL 2048
#define SS 2048
#define HH 8
#define EE 64
#define NTOK (BB * SS * HH)          // 32768

__device__ float g_qev[(size_t)NTOK * EE];       // quantum-encoded values, fp32
__device__ __half g_kh[(size_t)NTOK * EE];       // K, half, e pair-permuted
__device__ __half g_vt[(size_t)16 * EE * SS];    // qev, half, transposed [bh][e][s-perm]
__device__ int g_ctr;

// pair permutation within groups of 8 half-pairs (16 halves):
// pair j -> physical slot p = 2*(j&3) + (j>>2)

// ---------------------------------------------------------------------------
// Quantum circuit helpers (4 qubits, 16 complex amplitudes, wire 0 = MSB)
// ---------------------------------------------------------------------------
template <int W>
__device__ __forceinline__ void apply_ry(float* ar, float* ai, float th) {
    float s, c;
    __sincosf(th * 0.5f, &s, &c);
    const int mask = 8 >> W;
#pragma unroll
    for (int i = 0; i < 16; i++) {
        if ((i & mask) == 0) {
            const int j = i | mask;
            float r0 = ar[i], i0 = ai[i], r1 = ar[j], i1 = ai[j];
            ar[i] = c * r0 - s * r1;  ai[i] = c * i0 - s * i1;
            ar[j] = s * r0 + c * r1;  ai[j] = s * i0 + c * i1;
        }
    }
}

template <int C, int T>
__device__ __forceinline__ void apply_crx(float* ar, float* ai, float th) {
    float s, c;
    __sincosf(th * 0.5f, &s, &c);
    const int cm = 8 >> C, tm = 8 >> T;
#pragma unroll
    for (int i = 0; i < 16; i++) {
        if ((i & cm) != 0 && (i & tm) == 0) {
            const int j = i | tm;
            float r0 = ar[i], i0 = ai[i], r1 = ar[j], i1 = ai[j];
            ar[i] = c * r0 + s * i1;  ai[i] = c * i0 - s * r1;
            ar[j] = c * r1 + s * i0;  ai[j] = c * i1 - s * r0;
        }
    }
}

template <int W>
__device__ __forceinline__ void measure_xyz_w(const float* ar, const float* ai,
                                              float* meas) {
    const int mask = 8 >> W;
    float pr = 0.f, pi = 0.f, z = 0.f;
#pragma unroll
    for (int i = 0; i < 16; i++) {
        if ((i & mask) == 0) {
            const int j = i | mask;
            pr += ar[i] * ar[j] + ai[i] * ai[j];
            pi += ar[i] * ai[j] - ai[i] * ar[j];
            z  += ar[i] * ar[i] + ai[i] * ai[i]
                - ar[j] * ar[j] - ai[j] * ai[j];
        }
    }
    meas[W]     = 2.0f * pr;
    meas[4 + W] = 2.0f * pi;
    meas[8 + W] = z;
}

// pack 4 float4 (16 logical e) into 8 pair-permuted half2 words
__device__ __forceinline__ void pack_perm16(const float4& l0, const float4& l1,
                                            const float4& l2, const float4& l3,
                                            __half2* w) {
    w[0] = __floats2half2_rn(l0.x, l0.y);
    w[1] = __floats2half2_rn(l2.x, l2.y);
    w[2] = __floats2half2_rn(l0.z, l0.w);
    w[3] = __floats2half2_rn(l2.z, l2.w);
    w[4] = __floats2half2_rn(l1.x, l1.y);
    w[5] = __floats2half2_rn(l3.x, l3.y);
    w[6] = __floats2half2_rn(l1.z, l1.w);
    w[7] = __floats2half2_rn(l3.z, l3.w);
}

// ---------------------------------------------------------------------------
// Kernel 1: values -> angles -> PQC -> expvals -> qev  + K -> half (permuted)
// ---------------------------------------------------------------------------
__global__ __launch_bounds__(256) void quantum_kernel(
    const float* __restrict__ values, const float* __restrict__ Kin,
    const float* __restrict__ W_ang, const float* __restrict__ b_ang,
    const float* __restrict__ W_out, const float* __restrict__ b_out) {
    __shared__ float sW[16 * 64];
    __shared__ float sb[16];
    __shared__ float sWo[64 * 12];
    __shared__ float sbo[64];
    int tid = threadIdx.x;
    if (blockIdx.x == 0 && tid == 0) g_ctr = 0;
    for (int i = tid; i < 16 * 64; i += 256) sW[i] = W_ang[i];
    for (int i = tid; i < 64 * 12; i += 256) sWo[i] = W_out[i];
    if (tid < 16) sb[tid] = b_ang[tid];
    if (tid < 64) sbo[tid] = b_out[tid];
    __syncthreads();

    int t = blockIdx.x * 256 + tid;

    // --- K -> half, pair-permuted ---
    {
        const float4* k4 = (const float4*)(Kin + (size_t)t * EE);
        __half2* ko = (__half2*)(g_kh + (size_t)t * EE);
#pragma unroll
        for (int grp = 0; grp < 4; grp++) {
            float4 l0 = k4[grp * 4 + 0], l1 = k4[grp * 4 + 1];
            float4 l2 = k4[grp * 4 + 2], l3 = k4[grp * 4 + 3];
            __align__(16) __half2 w[8];
            pack_perm16(l0, l1, l2, l3, w);
            *(uint4*)(ko + grp * 8)     = *(const uint4*)(w);
            *(uint4*)(ko + grp * 8 + 4) = *(const uint4*)(w + 4);
        }
    }

    const float4* v4 = (const float4*)(values + (size_t)t * EE);

    float ang[16];
#pragma unroll
    for (int p = 0; p < 16; p++) ang[p] = sb[p];
#pragma unroll
    for (int eg = 0; eg < 16; eg++) {
        float4 v = v4[eg];
#pragma unroll
        for (int p = 0; p < 16; p++) {
            const float* w = &sW[p * 64 + eg * 4];
            ang[p] += w[0] * v.x + w[1] * v.y + w[2] * v.z + w[3] * v.w;
        }
    }

    float ar[16], ai[16];
#pragma unroll
    for (int i = 0; i < 16; i++) { ar[i] = 0.f; ai[i] = 0.f; }
    ar[0] = 1.0f;

    apply_ry<0>(ar, ai, ang[0]);
    apply_ry<1>(ar, ai, ang[1]);
    apply_ry<2>(ar, ai, ang[2]);
    apply_ry<3>(ar, ai, ang[3]);
    apply_crx<3, 0>(ar, ai, ang[4]);
    apply_crx<2, 3>(ar, ai, ang[5]);
    apply_crx<1, 2>(ar, ai, ang[6]);
    apply_crx<0, 1>(ar, ai, ang[7]);
    apply_ry<0>(ar, ai, ang[8]);
    apply_ry<1>(ar, ai, ang[9]);
    apply_ry<2>(ar, ai, ang[10]);
    apply_ry<3>(ar, ai, ang[11]);
    apply_crx<3, 2>(ar, ai, ang[12]);
    apply_crx<0, 3>(ar, ai, ang[13]);
    apply_crx<1, 0>(ar, ai, ang[14]);
    apply_crx<2, 1>(ar, ai, ang[15]);

    float meas[12];
    measure_xyz_w<0>(ar, ai, meas);
    measure_xyz_w<1>(ar, ai, meas);
    measure_xyz_w<2>(ar, ai, meas);
    measure_xyz_w<3>(ar, ai, meas);

    float4* o4 = (float4*)(g_qev + (size_t)t * EE);
#pragma unroll
    for (int eg = 0; eg < 16; eg++) {
        float r[4];
#pragma unroll
        for (int q = 0; q < 4; q++) {
            int e = eg * 4 + q;
            float acc = sbo[e];
            const float* w = &sWo[e * 12];
#pragma unroll
            for (int mm = 0; mm < 12; mm++) acc += meas[mm] * w[mm];
            r[q] = acc;
        }
        o4[eg] = make_float4(r[0], r[1], r[2], r[3]);
    }
}

// ---------------------------------------------------------------------------
// Kernel 1b: qev (fp32 [B,S,H,E]) -> g_vt (half, [bh][e][s], s pair-permuted)
// ---------------------------------------------------------------------------
__global__ __launch_bounds__(256) void vt_kernel() {
    __shared__ float tile[64][65];
    const int bh = blockIdx.y;          // b*8+h
    const int b = bh >> 3, h = bh & 7;
    const int s0 = blockIdx.x * 64;
    const int tid = threadIdx.x;

    // load 64 tokens x 64 e
    for (int task = tid; task < 1024; task += 256) {
        int row = task >> 4, eg = task & 15;
        const float4 v = *(const float4*)(
            g_qev + ((size_t)(b * SS + s0 + row) * HH + h) * EE + eg * 4);
        tile[row][eg * 4 + 0] = v.x;
        tile[row][eg * 4 + 1] = v.y;
        tile[row][eg * 4 + 2] = v.z;
        tile[row][eg * 4 + 3] = v.w;
    }
    __syncthreads();

    // write 64 e-rows x 32 half2 words, s pair-permuted within 16-groups
    for (int task = tid; task < 2048; task += 256) {
        int e = task >> 5, w = task & 31;
        int grp = w >> 3, pw = w & 7;
        int j = (pw & 1) ? ((pw >> 1) + 4) : (pw >> 1);   // inverse perm
        int sl = grp * 16 + 2 * j;
        __half2 h2 = __floats2half2_rn(tile[sl][e], tile[sl + 1][e]);
        *((__half2*)(g_vt + ((size_t)(bh * 64 + e) * SS + s0)) + w) = h2;
    }
}

// ---------------------------------------------------------------------------
// Kernel 2: persistent causal flash attention, fp16 mma m16n8k16
// BM=128 rows/item, 8 warps * 16 rows, BN=64 keys/iter, E=64
// smem strides: 40 words (160B) per 64-half row -> conflict-free LDS.64 frags
// ---------------------------------------------------------------------------
#define BM 128
#define BN 64
#define RW 40            // row stride in 32-bit words for all smem arrays
#define N_ITEMS 256
#define SM_WORDS (BM * RW + BM * RW + 2 * BN * RW + 2 * BN * RW)
#define SMEM_BYTES (SM_WORDS * 4)

__device__ __forceinline__ void mma16(float* d, uint32_t a0, uint32_t a1,
                                      uint32_t a2, uint32_t a3,
                                      uint32_t b0, uint32_t b1) {
    asm volatile(
        "mma.sync.aligned.m16n8k16.row.col.f32.f16.f16.f32 "
        "{%0,%1,%2,%3}, {%4,%5,%6,%7}, {%8,%9}, {%0,%1,%2,%3};"
        : "+f"(d[0]), "+f"(d[1]), "+f"(d[2]), "+f"(d[3])
        : "r"(a0), "r"(a1), "r"(a2), "r"(a3), "r"(b0), "r"(b1));
}

__device__ __forceinline__ void cp16(uint32_t saddr, const void* g) {
    asm volatile("cp.async.cg.shared.global [%0], [%1], 16;"
                 :: "r"(saddr), "l"(g));
}
__device__ __forceinline__ void cp_commit() {
    asm volatile("cp.async.commit_group;");
}
__device__ __forceinline__ void cp_wait0() {
    asm volatile("cp.async.wait_group 0;");
}

__global__ __launch_bounds__(256, 1) void attn_kernel(
    const float* __restrict__ Q, float* __restrict__ Out) {
    extern __shared__ uint32_t sm[];
    uint32_t* Qs = sm;                       // [row][32w] half2, e-permuted
    uint32_t* Ps = Qs + BM * RW;             // [row][32w] half2, key-permuted
    uint32_t* Ks0 = Ps + BM * RW;            // 2 x [key][32w] half2, e-permuted
    uint32_t* Vs0 = Ks0 + 2 * BN * RW;       // 2 x [e][32w] half2, key-permuted
    __shared__ int sItem;

    const int tid = threadIdx.x;
    const int wid = tid >> 5, lane = tid & 31;
    const int g = lane >> 2, t = lane & 3;
    const int R0 = wid * 16;
    const size_t rs = (size_t)HH * EE;       // 512
    const float scale = 0.125f;

    const uint32_t sK = (uint32_t)__cvta_generic_to_shared(Ks0);
    const uint32_t sV = (uint32_t)__cvta_generic_to_shared(Vs0);

    for (;;) {
        if (tid == 0) sItem = atomicAdd(&g_ctr, 1);
        __syncthreads();
        const int item = sItem;
        if (item >= N_ITEMS) break;

        const int bh = item & 15;
        const int qblk = 15 - (item >> 4);   // big q-blocks first
        const int b = bh >> 3, h = bh & 7;
        const int qbase = qblk * BM;
        const size_t base = (size_t)b * SS * rs + (size_t)h * EE;
        const size_t khbase = base;          // g_kh same token layout
        const size_t vtbase = (size_t)bh * 64 * SS;

        // ---- load Q tile -> half, pair-permuted ----
#pragma unroll
        for (int p = 0; p < 2; p++) {
            int task = tid + 256 * p;
            int row = task >> 2, grp = task & 3;
            const float4* qg = (const float4*)(
                Q + base + (size_t)(qbase + row) * rs + grp * 16);
            float4 l0 = qg[0], l1 = qg[1], l2 = qg[2], l3 = qg[3];
            __align__(16) __half2 w[8];
            pack_perm16(l0, l1, l2, l3, w);
            uint32_t* qrow = Qs + row * RW + grp * 8;
            *(uint4*)(qrow)     = *(const uint4*)(w);
            *(uint4*)(qrow + 4) = *(const uint4*)(w + 4);
        }

        const int kb_end = 2 * qblk + 1;

        // ---- prologue: prefetch tile 0 (K: 512 cp16, V: 512 cp16) ----
#pragma unroll
        for (int p = 0; p < 4; p++) {
            int task = tid + 256 * p;
            if (task < 512) {
                int row = task >> 3, seg = task & 7;
                const __half* gk = g_kh + khbase + (size_t)row * rs + seg * 8;
                cp16(sK + (row * RW + seg * 4) * 4, gk);
            } else {
                int e = (task - 512) >> 3, seg = task & 7;
                const __half* gv = g_vt + vtbase + (size_t)e * SS + seg * 8;
                cp16(sV + (e * RW + seg * 4) * 4, gv);
            }
        }
        cp_commit();

        float o[8][4];
#pragma unroll
        for (int nt = 0; nt < 8; nt++)
#pragma unroll
            for (int j = 0; j < 4; j++) o[nt][j] = 0.f;
        float m0 = -1e30f, m1 = -1e30f, l0v = 0.f, l1v = 0.f;

        for (int kb = 0; kb <= kb_end; kb++) {
            const int kbase = kb * BN;
            const uint32_t* Kb = Ks0 + (kb & 1) * BN * RW;
            const uint32_t* Vb = Vs0 + (kb & 1) * BN * RW;

            cp_wait0();
            __syncthreads();

            if (kb < kb_end) {
                const int nkbase = kbase + BN;
                const uint32_t oK = sK + ((kb + 1) & 1) * BN * RW * 4;
                const uint32_t oV = sV + ((kb + 1) & 1) * BN * RW * 4;
#pragma unroll
                for (int p = 0; p < 4; p++) {
                    int task = tid + 256 * p;
                    if (task < 512) {
                        int row = task >> 3, seg = task & 7;
                        const __half* gk =
                            g_kh + khbase + (size_t)(nkbase + row) * rs + seg * 8;
                        cp16(oK + (row * RW + seg * 4) * 4, gk);
                    } else {
                        int e = (task - 512) >> 3, seg = task & 7;
                        const __half* gv =
                            g_vt + vtbase + (size_t)e * SS + nkbase + seg * 8;
                        cp16(oV + (e * RW + seg * 4) * 4, gv);
                    }
                }
                cp_commit();
            }

            // ---- S = Q K^T : 4 ksteps (k16) x 8 ntiles ----
            float s[8][4];
#pragma unroll
            for (int nt = 0; nt < 8; nt++)
#pragma unroll
                for (int j = 0; j < 4; j++) s[nt][j] = 0.f;

#pragma unroll
            for (int ks = 0; ks < 4; ks++) {
                const uint2 A0 = *(const uint2*)(Qs + (R0 + g) * RW + ks * 8 + 2 * t);
                const uint2 A1 = *(const uint2*)(Qs + (R0 + g + 8) * RW + ks * 8 + 2 * t);
#pragma unroll
                for (int nt = 0; nt < 8; nt++) {
                    const uint2 Bf =
                        *(const uint2*)(Kb + (nt * 8 + g) * RW + ks * 8 + 2 * t);
                    mma16(s[nt], A0.x, A1.x, A0.y, A1.y, Bf.x, Bf.y);
                }
            }

            // ---- scale + causal mask ----
            if (kb >= 2 * qblk) {
                const int row0 = qbase + R0 + g, row1 = row0 + 8;
#pragma unroll
                for (int nt = 0; nt < 8; nt++) {
                    int c0 = kbase + nt * 8 + 2 * t, c1 = c0 + 1;
                    s[nt][0] = (c0 > row0) ? -1e9f : s[nt][0] * scale;
                    s[nt][1] = (c1 > row0) ? -1e9f : s[nt][1] * scale;
                    s[nt][2] = (c0 > row1) ? -1e9f : s[nt][2] * scale;
                    s[nt][3] = (c1 > row1) ? -1e9f : s[nt][3] * scale;
                }
            } else {
#pragma unroll
                for (int nt = 0; nt < 8; nt++)
#pragma unroll
                    for (int j = 0; j < 4; j++) s[nt][j] *= scale;
            }

            // ---- online softmax ----
            float rm0 = -1e30f, rm1 = -1e30f;
#pragma unroll
            for (int nt = 0; nt < 8; nt++) {
                rm0 = fmaxf(rm0, fmaxf(s[nt][0], s[nt][1]));
                rm1 = fmaxf(rm1, fmaxf(s[nt][2], s[nt][3]));
            }
            rm0 = fmaxf(rm0, __shfl_xor_sync(0xffffffffu, rm0, 1));
            rm0 = fmaxf(rm0, __shfl_xor_sync(0xffffffffu, rm0, 2));
            rm1 = fmaxf(rm1, __shfl_xor_sync(0xffffffffu, rm1, 1));
            rm1 = fmaxf(rm1, __shfl_xor_sync(0xffffffffu, rm1, 2));

            float mn0 = fmaxf(m0, rm0), mn1 = fmaxf(m1, rm1);
            float al0 = __expf(m0 - mn0), al1 = __expf(m1 - mn1);
            m0 = mn0; m1 = mn1;
            float rs0 = 0.f, rs1 = 0.f;
#pragma unroll
            for (int nt = 0; nt < 8; nt++) {
                s[nt][0] = __expf(s[nt][0] - mn0);
                s[nt][1] = __expf(s[nt][1] - mn0);
                s[nt][2] = __expf(s[nt][2] - mn1);
                s[nt][3] = __expf(s[nt][3] - mn1);
                rs0 += s[nt][0] + s[nt][1];
                rs1 += s[nt][2] + s[nt][3];
            }
            rs0 += __shfl_xor_sync(0xffffffffu, rs0, 1);
            rs0 += __shfl_xor_sync(0xffffffffu, rs0, 2);
            rs1 += __shfl_xor_sync(0xffffffffu, rs1, 1);
            rs1 += __shfl_xor_sync(0xffffffffu, rs1, 2);
            l0v = l0v * al0 + rs0;
            l1v = l1v * al1 + rs1;
#pragma unroll
            for (int nt = 0; nt < 8; nt++) {
                o[nt][0] *= al0; o[nt][1] *= al0;
                o[nt][2] *= al1; o[nt][3] *= al1;
            }

            // ---- P -> smem as half2, key pair-permuted ----
            // pair (nt*4+t): group nt>>1, j = (nt&1)*4+t, slot = 2t+(nt&1)
#pragma unroll
            for (int nt = 0; nt < 8; nt++) {
                const int wrd = (nt >> 1) * 8 + 2 * t + (nt & 1);
                *(__half2*)(Ps + (R0 + g) * RW + wrd) =
                    __floats2half2_rn(s[nt][0], s[nt][1]);
                *(__half2*)(Ps + (R0 + g + 8) * RW + wrd) =
                    __floats2half2_rn(s[nt][2], s[nt][3]);
            }
            __syncwarp();

            // ---- O += P V ----
#pragma unroll
            for (int ks = 0; ks < 4; ks++) {
                const uint2 A0 = *(const uint2*)(Ps + (R0 + g) * RW + ks * 8 + 2 * t);
                const uint2 A1 = *(const uint2*)(Ps + (R0 + g + 8) * RW + ks * 8 + 2 * t);
#pragma unroll
                for (int nt = 0; nt < 8; nt++) {
                    const uint2 Bf =
                        *(const uint2*)(Vb + (nt * 8 + g) * RW + ks * 8 + 2 * t);
                    mma16(o[nt], A0.x, A1.x, A0.y, A1.y, Bf.x, Bf.y);
                }
            }
        }

        // ---- normalize + store ----
        const float i0 = 1.0f / l0v, i1 = 1.0f / l1v;
        const size_t out0 = base + (size_t)(qbase + R0 + g) * rs;
        const size_t out1 = base + (size_t)(qbase + R0 + g + 8) * rs;
#pragma unroll
        for (int nt = 0; nt < 8; nt++) {
            const int cc = nt * 8 + 2 * t;
            *(float2*)(Out + out0 + cc) = make_float2(o[nt][0] * i0, o[nt][1] * i0);
            *(float2*)(Out + out1 + cc) = make_float2(o[nt][2] * i1, o[nt][3] * i1);
        }
    }
}

// ---------------------------------------------------------------------------
extern "C" void kernel_launch(void* const* d_in, const int* in_sizes, int n_in,
                              void* d_out, int out_size) {
    const float* Q  = (const float*)d_in[0];
    const float* K  = (const float*)d_in[1];
    const float* V  = (const float*)d_in[2];
    const float* Wa = (const float*)d_in[3];
    const float* ba = (const float*)d_in[4];
    const float* Wo = (const float*)d_in[5];
    const float* bo = (const float*)d_in[6];
    float* Out = (float*)d_out;

    cudaFuncSetAttribute(attn_kernel, cudaFuncAttributeMaxDynamicSharedMemorySize,
                         SMEM_BYTES);

    quantum_kernel<<<NTOK / 256, 256>>>(V, K, Wa, ba, Wo, bo);
    dim3 vgrid(SS / 64, BB * HH);
    vt_kernel<<<vgrid, 256>>>();
    attn_kernel<<<148, 256, SMEM_BYTES>>>(Q, Out);
}

// round 5
// speedup vs baseline: 5.5703x; 1.0343x over previous
#include <cuda_runtime.h>
#include <cuda_fp16.h>
#include <cstdint>
#include <math.h>

// Problem constants
#define BB 2
#define LL 2048
#define SS 2048
#define HH 8
#define EE 64
#define NTOK (BB * SS * HH)          // 32768

__device__ __half g_qevh[(size_t)NTOK * EE];     // quantum-encoded values, half
__device__ __half g_kh[(size_t)NTOK * EE];       // K, half, e pair-permuted
__device__ __half g_vt[(size_t)16 * EE * SS];    // qev, half, transposed [bh][e][s-perm]
__device__ int g_ctr;

// pair permutation within groups of 8 half-pairs (16 halves):
// pair j -> physical slot p = 2*(j&3) + (j>>2)

// ---------------------------------------------------------------------------
// Quantum circuit helpers (4 qubits, 16 complex amplitudes, wire 0 = MSB)
// ---------------------------------------------------------------------------
template <int W>
__device__ __forceinline__ void apply_ry(float* ar, float* ai, float th) {
    float s, c;
    __sincosf(th * 0.5f, &s, &c);
    const int mask = 8 >> W;
#pragma unroll
    for (int i = 0; i < 16; i++) {
        if ((i & mask) == 0) {
            const int j = i | mask;
            float r0 = ar[i], i0 = ai[i], r1 = ar[j], i1 = ai[j];
            ar[i] = c * r0 - s * r1;  ai[i] = c * i0 - s * i1;
            ar[j] = s * r0 + c * r1;  ai[j] = s * i0 + c * i1;
        }
    }
}

template <int C, int T>
__device__ __forceinline__ void apply_crx(float* ar, float* ai, float th) {
    float s, c;
    __sincosf(th * 0.5f, &s, &c);
    const int cm = 8 >> C, tm = 8 >> T;
#pragma unroll
    for (int i = 0; i < 16; i++) {
        if ((i & cm) != 0 && (i & tm) == 0) {
            const int j = i | tm;
            float r0 = ar[i], i0 = ai[i], r1 = ar[j], i1 = ai[j];
            ar[i] = c * r0 + s * i1;  ai[i] = c * i0 - s * r1;
            ar[j] = c * r1 + s * i0;  ai[j] = c * i1 - s * r0;
        }
    }
}

template <int W>
__device__ __forceinline__ void measure_xyz_w(const float* ar, const float* ai,
                                              float* meas) {
    const int mask = 8 >> W;
    float pr = 0.f, pi = 0.f, z = 0.f;
#pragma unroll
    for (int i = 0; i < 16; i++) {
        if ((i & mask) == 0) {
            const int j = i | mask;
            pr += ar[i] * ar[j] + ai[i] * ai[j];
            pi += ar[i] * ai[j] - ai[i] * ar[j];
            z  += ar[i] * ar[i] + ai[i] * ai[i]
                - ar[j] * ar[j] - ai[j] * ai[j];
        }
    }
    meas[W]     = 2.0f * pr;
    meas[4 + W] = 2.0f * pi;
    meas[8 + W] = z;
}

// pack 4 float4 (16 logical e) into 8 pair-permuted half2 words
__device__ __forceinline__ void pack_perm16(const float4& l0, const float4& l1,
                                            const float4& l2, const float4& l3,
                                            __half2* w) {
    w[0] = __floats2half2_rn(l0.x, l0.y);
    w[1] = __floats2half2_rn(l2.x, l2.y);
    w[2] = __floats2half2_rn(l0.z, l0.w);
    w[3] = __floats2half2_rn(l2.z, l2.w);
    w[4] = __floats2half2_rn(l1.x, l1.y);
    w[5] = __floats2half2_rn(l3.x, l3.y);
    w[6] = __floats2half2_rn(l1.z, l1.w);
    w[7] = __floats2half2_rn(l3.z, l3.w);
}

// ---------------------------------------------------------------------------
// Kernel 1: values -> angles -> PQC -> expvals -> qev(half) + K -> half (perm)
// ---------------------------------------------------------------------------
__global__ __launch_bounds__(256, 1) void quantum_kernel(
    const float* __restrict__ values, const float* __restrict__ Kin,
    const float* __restrict__ W_ang, const float* __restrict__ b_ang,
    const float* __restrict__ W_out, const float* __restrict__ b_out) {
    __shared__ float sW[16 * 64];
    __shared__ float sb[16];
    __shared__ float sWo[64 * 12];
    __shared__ float sbo[64];
    int tid = threadIdx.x;
    if (blockIdx.x == 0 && tid == 0) g_ctr = 0;
    for (int i = tid; i < 16 * 64; i += 256) sW[i] = W_ang[i];
    for (int i = tid; i < 64 * 12; i += 256) sWo[i] = W_out[i];
    if (tid < 16) sb[tid] = b_ang[tid];
    if (tid < 64) sbo[tid] = b_out[tid];
    __syncthreads();

    int t = blockIdx.x * 256 + tid;

    // --- K -> half, pair-permuted ---
    {
        const float4* k4 = (const float4*)(Kin + (size_t)t * EE);
        __half2* ko = (__half2*)(g_kh + (size_t)t * EE);
#pragma unroll
        for (int grp = 0; grp < 4; grp++) {
            float4 l0 = k4[grp * 4 + 0], l1 = k4[grp * 4 + 1];
            float4 l2 = k4[grp * 4 + 2], l3 = k4[grp * 4 + 3];
            __align__(16) __half2 w[8];
            pack_perm16(l0, l1, l2, l3, w);
            *(uint4*)(ko + grp * 8)     = *(const uint4*)(w);
            *(uint4*)(ko + grp * 8 + 4) = *(const uint4*)(w + 4);
        }
    }

    const float4* v4 = (const float4*)(values + (size_t)t * EE);

    float ang[16];
#pragma unroll
    for (int p = 0; p < 16; p++) ang[p] = sb[p];
#pragma unroll
    for (int eg = 0; eg < 16; eg++) {
        float4 v = v4[eg];
#pragma unroll
        for (int p = 0; p < 16; p++) {
            const float* w = &sW[p * 64 + eg * 4];
            ang[p] += w[0] * v.x + w[1] * v.y + w[2] * v.z + w[3] * v.w;
        }
    }

    float ar[16], ai[16];
#pragma unroll
    for (int i = 0; i < 16; i++) { ar[i] = 0.f; ai[i] = 0.f; }
    ar[0] = 1.0f;

    apply_ry<0>(ar, ai, ang[0]);
    apply_ry<1>(ar, ai, ang[1]);
    apply_ry<2>(ar, ai, ang[2]);
    apply_ry<3>(ar, ai, ang[3]);
    apply_crx<3, 0>(ar, ai, ang[4]);
    apply_crx<2, 3>(ar, ai, ang[5]);
    apply_crx<1, 2>(ar, ai, ang[6]);
    apply_crx<0, 1>(ar, ai, ang[7]);
    apply_ry<0>(ar, ai, ang[8]);
    apply_ry<1>(ar, ai, ang[9]);
    apply_ry<2>(ar, ai, ang[10]);
    apply_ry<3>(ar, ai, ang[11]);
    apply_crx<3, 2>(ar, ai, ang[12]);
    apply_crx<0, 3>(ar, ai, ang[13]);
    apply_crx<1, 0>(ar, ai, ang[14]);
    apply_crx<2, 1>(ar, ai, ang[15]);

    float meas[12];
    measure_xyz_w<0>(ar, ai, meas);
    measure_xyz_w<1>(ar, ai, meas);
    measure_xyz_w<2>(ar, ai, meas);
    measure_xyz_w<3>(ar, ai, meas);

    // qev (half) = meas @ W_out^T + b_out
    __half2* o2 = (__half2*)(g_qevh + (size_t)t * EE);
#pragma unroll
    for (int eg = 0; eg < 8; eg++) {
        __align__(16) __half2 w[4];
#pragma unroll
        for (int q = 0; q < 4; q++) {
            int e0 = eg * 8 + 2 * q, e1 = e0 + 1;
            float a0 = sbo[e0], a1 = sbo[e1];
            const float* w0 = &sWo[e0 * 12];
            const float* w1 = &sWo[e1 * 12];
#pragma unroll
            for (int mm = 0; mm < 12; mm++) {
                a0 += meas[mm] * w0[mm];
                a1 += meas[mm] * w1[mm];
            }
            w[q] = __floats2half2_rn(a0, a1);
        }
        *(uint4*)(o2 + eg * 4) = *(const uint4*)(w);
    }
}

// ---------------------------------------------------------------------------
// Kernel 1b: g_qevh (half [B,S,H,E]) -> g_vt (half [bh][e][s], s pair-permuted)
// ---------------------------------------------------------------------------
__global__ __launch_bounds__(256) void vt_kernel() {
    __shared__ __half tile[64][66];
    const int bh = blockIdx.y;          // b*8+h
    const int b = bh >> 3, h = bh & 7;
    const int s0 = blockIdx.x * 64;
    const int tid = threadIdx.x;

    // load 64 tokens x 64 e (half2 words)
    for (int task = tid; task < 2048; task += 256) {
        int row = task >> 5, w = task & 31;
        const __half2 v = *((const __half2*)(
            g_qevh + ((size_t)(b * SS + s0 + row) * HH + h) * EE) + w);
        *(__half2*)(&tile[row][2 * w]) = v;
    }
    __syncthreads();

    // write 64 e-rows x 32 half2 words, s pair-permuted within 16-groups
    for (int task = tid; task < 2048; task += 256) {
        int e = task >> 5, w = task & 31;
        int grp = w >> 3, pw = w & 7;
        int j = (pw & 1) ? ((pw >> 1) + 4) : (pw >> 1);   // inverse perm
        int sl = grp * 16 + 2 * j;
        __half2 h2;
        h2.x = tile[sl][e];
        h2.y = tile[sl + 1][e];
        *((__half2*)(g_vt + ((size_t)(bh * 64 + e) * SS + s0)) + w) = h2;
    }
}

// ---------------------------------------------------------------------------
// Kernel 2: persistent causal flash attention, fp16 mma m16n8k16
// BM=128 rows/item, 8 warps * 16 rows, BN=64 keys/iter, E=64
// Q A-fragments hoisted to registers (invariant over the K loop)
// ---------------------------------------------------------------------------
#define BM 128
#define BN 64
#define RW 40            // row stride in 32-bit words for all smem arrays
#define N_ITEMS 256
#define SM_WORDS (BM * RW + BM * RW + 2 * BN * RW + 2 * BN * RW)
#define SMEM_BYTES (SM_WORDS * 4)

__device__ __forceinline__ void mma16(float* d, uint32_t a0, uint32_t a1,
                                      uint32_t a2, uint32_t a3,
                                      uint32_t b0, uint32_t b1) {
    asm volatile(
        "mma.sync.aligned.m16n8k16.row.col.f32.f16.f16.f32 "
        "{%0,%1,%2,%3}, {%4,%5,%6,%7}, {%8,%9}, {%0,%1,%2,%3};"
        : "+f"(d[0]), "+f"(d[1]), "+f"(d[2]), "+f"(d[3])
        : "r"(a0), "r"(a1), "r"(a2), "r"(a3), "r"(b0), "r"(b1));
}

__device__ __forceinline__ void cp16(uint32_t saddr, const void* g) {
    asm volatile("cp.async.cg.shared.global [%0], [%1], 16;"
                 :: "r"(saddr), "l"(g));
}
__device__ __forceinline__ void cp_commit() {
    asm volatile("cp.async.commit_group;");
}
__device__ __forceinline__ void cp_wait0() {
    asm volatile("cp.async.wait_group 0;");
}

__global__ __launch_bounds__(256, 1) void attn_kernel(
    const float* __restrict__ Q, float* __restrict__ Out) {
    extern __shared__ uint32_t sm[];
    uint32_t* Qs = sm;                       // [row][32w] half2, e-permuted
    uint32_t* Ps = Qs + BM * RW;             // [row][32w] half2, key-permuted
    uint32_t* Ks0 = Ps + BM * RW;            // 2 x [key][32w] half2, e-permuted
    uint32_t* Vs0 = Ks0 + 2 * BN * RW;       // 2 x [e][32w] half2, key-permuted
    __shared__ int sItem;

    const int tid = threadIdx.x;
    const int wid = tid >> 5, lane = tid & 31;
    const int g = lane >> 2, t = lane & 3;
    const int R0 = wid * 16;
    const size_t rs = (size_t)HH * EE;       // 512
    const float scale = 0.125f;

    const uint32_t sK = (uint32_t)__cvta_generic_to_shared(Ks0);
    const uint32_t sV = (uint32_t)__cvta_generic_to_shared(Vs0);

    for (;;) {
        if (tid == 0) sItem = atomicAdd(&g_ctr, 1);
        __syncthreads();
        const int item = sItem;
        if (item >= N_ITEMS) break;

        const int bh = item & 15;
        const int qblk = 15 - (item >> 4);   // big q-blocks first
        const int b = bh >> 3, h = bh & 7;
        const int qbase = qblk * BM;
        const size_t base = (size_t)b * SS * rs + (size_t)h * EE;
        const size_t khbase = base;          // g_kh same token layout
        const size_t vtbase = (size_t)bh * 64 * SS;

        // ---- load Q tile -> half, pair-permuted ----
#pragma unroll
        for (int p = 0; p < 2; p++) {
            int task = tid + 256 * p;
            int row = task >> 2, grp = task & 3;
            const float4* qg = (const float4*)(
                Q + base + (size_t)(qbase + row) * rs + grp * 16);
            float4 l0 = qg[0], l1 = qg[1], l2 = qg[2], l3 = qg[3];
            __align__(16) __half2 w[8];
            pack_perm16(l0, l1, l2, l3, w);
            uint32_t* qrow = Qs + row * RW + grp * 8;
            *(uint4*)(qrow)     = *(const uint4*)(w);
            *(uint4*)(qrow + 4) = *(const uint4*)(w + 4);
        }

        const int kb_end = 2 * qblk + 1;

        // ---- prologue: prefetch tile 0 (K: 512 cp16, V: 512 cp16) ----
#pragma unroll
        for (int p = 0; p < 4; p++) {
            int task = tid + 256 * p;
            if (task < 512) {
                int row = task >> 3, seg = task & 7;
                const __half* gk = g_kh + khbase + (size_t)row * rs + seg * 8;
                cp16(sK + (row * RW + seg * 4) * 4, gk);
            } else {
                int e = (task - 512) >> 3, seg = task & 7;
                const __half* gv = g_vt + vtbase + (size_t)e * SS + seg * 8;
                cp16(sV + (e * RW + seg * 4) * 4, gv);
            }
        }
        cp_commit();

        // ---- hoist Q A-fragments into registers (invariant per item) ----
        __syncthreads();   // Qs visible to all lanes
        uint32_t qa[4][4];
#pragma unroll
        for (int ks = 0; ks < 4; ks++) {
            const uint2 A0 = *(const uint2*)(Qs + (R0 + g) * RW + ks * 8 + 2 * t);
            const uint2 A1 = *(const uint2*)(Qs + (R0 + g + 8) * RW + ks * 8 + 2 * t);
            qa[ks][0] = A0.x; qa[ks][1] = A1.x;
            qa[ks][2] = A0.y; qa[ks][3] = A1.y;
        }

        float o[8][4];
#pragma unroll
        for (int nt = 0; nt < 8; nt++)
#pragma unroll
            for (int j = 0; j < 4; j++) o[nt][j] = 0.f;
        float m0 = -1e30f, m1 = -1e30f, l0v = 0.f, l1v = 0.f;

        for (int kb = 0; kb <= kb_end; kb++) {
            const int kbase = kb * BN;
            const uint32_t* Kb = Ks0 + (kb & 1) * BN * RW;
            const uint32_t* Vb = Vs0 + (kb & 1) * BN * RW;

            cp_wait0();
            __syncthreads();

            if (kb < kb_end) {
                const int nkbase = kbase + BN;
                const uint32_t oK = sK + ((kb + 1) & 1) * BN * RW * 4;
                const uint32_t oV = sV + ((kb + 1) & 1) * BN * RW * 4;
#pragma unroll
                for (int p = 0; p < 4; p++) {
                    int task = tid + 256 * p;
                    if (task < 512) {
                        int row = task >> 3, seg = task & 7;
                        const __half* gk =
                            g_kh + khbase + (size_t)(nkbase + row) * rs + seg * 8;
                        cp16(oK + (row * RW + seg * 4) * 4, gk);
                    } else {
                        int e = (task - 512) >> 3, seg = task & 7;
                        const __half* gv =
                            g_vt + vtbase + (size_t)e * SS + nkbase + seg * 8;
                        cp16(oV + (e * RW + seg * 4) * 4, gv);
                    }
                }
                cp_commit();
            }

            // ---- S = Q K^T : 4 ksteps (k16) x 8 ntiles ----
            float s[8][4];
#pragma unroll
            for (int nt = 0; nt < 8; nt++)
#pragma unroll
                for (int j = 0; j < 4; j++) s[nt][j] = 0.f;

#pragma unroll
            for (int ks = 0; ks < 4; ks++) {
#pragma unroll
                for (int nt = 0; nt < 8; nt++) {
                    const uint2 Bf =
                        *(const uint2*)(Kb + (nt * 8 + g) * RW + ks * 8 + 2 * t);
                    mma16(s[nt], qa[ks][0], qa[ks][1], qa[ks][2], qa[ks][3],
                          Bf.x, Bf.y);
                }
            }

            // ---- scale + causal mask ----
            if (kb >= 2 * qblk) {
                const int row0 = qbase + R0 + g, row1 = row0 + 8;
#pragma unroll
                for (int nt = 0; nt < 8; nt++) {
                    int c0 = kbase + nt * 8 + 2 * t, c1 = c0 + 1;
                    s[nt][0] = (c0 > row0) ? -1e9f : s[nt][0] * scale;
                    s[nt][1] = (c1 > row0) ? -1e9f : s[nt][1] * scale;
                    s[nt][2] = (c0 > row1) ? -1e9f : s[nt][2] * scale;
                    s[nt][3] = (c1 > row1) ? -1e9f : s[nt][3] * scale;
                }
            } else {
#pragma unroll
                for (int nt = 0; nt < 8; nt++)
#pragma unroll
                    for (int j = 0; j < 4; j++) s[nt][j] *= scale;
            }

            // ---- online softmax ----
            float rm0 = -1e30f, rm1 = -1e30f;
#pragma unroll
            for (int nt = 0; nt < 8; nt++) {
                rm0 = fmaxf(rm0, fmaxf(s[nt][0], s[nt][1]));
                rm1 = fmaxf(rm1, fmaxf(s[nt][2], s[nt][3]));
            }
            rm0 = fmaxf(rm0, __shfl_xor_sync(0xffffffffu, rm0, 1));
            rm0 = fmaxf(rm0, __shfl_xor_sync(0xffffffffu, rm0, 2));
            rm1 = fmaxf(rm1, __shfl_xor_sync(0xffffffffu, rm1, 1));
            rm1 = fmaxf(rm1, __shfl_xor_sync(0xffffffffu, rm1, 2));

            float mn0 = fmaxf(m0, rm0), mn1 = fmaxf(m1, rm1);
            float al0 = __expf(m0 - mn0), al1 = __expf(m1 - mn1);
            m0 = mn0; m1 = mn1;
            float rs0 = 0.f, rs1 = 0.f;
#pragma unroll
            for (int nt = 0; nt < 8; nt++) {
                s[nt][0] = __expf(s[nt][0] - mn0);
                s[nt][1] = __expf(s[nt][1] - mn0);
                s[nt][2] = __expf(s[nt][2] - mn1);
                s[nt][3] = __expf(s[nt][3] - mn1);
                rs0 += s[nt][0] + s[nt][1];
                rs1 += s[nt][2] + s[nt][3];
            }
            rs0 += __shfl_xor_sync(0xffffffffu, rs0, 1);
            rs0 += __shfl_xor_sync(0xffffffffu, rs0, 2);
            rs1 += __shfl_xor_sync(0xffffffffu, rs1, 1);
            rs1 += __shfl_xor_sync(0xffffffffu, rs1, 2);
            l0v = l0v * al0 + rs0;
            l1v = l1v * al1 + rs1;
#pragma unroll
            for (int nt = 0; nt < 8; nt++) {
                o[nt][0] *= al0; o[nt][1] *= al0;
                o[nt][2] *= al1; o[nt][3] *= al1;
            }

            // ---- P -> smem as half2, key pair-permuted ----
#pragma unroll
            for (int nt = 0; nt < 8; nt++) {
                const int wrd = (nt >> 1) * 8 + 2 * t + (nt & 1);
                *(__half2*)(Ps + (R0 + g) * RW + wrd) =
                    __floats2half2_rn(s[nt][0], s[nt][1]);
                *(__half2*)(Ps + (R0 + g + 8) * RW + wrd) =
                    __floats2half2_rn(s[nt][2], s[nt][3]);
            }
            __syncwarp();

            // ---- O += P V ----
#pragma unroll
            for (int ks = 0; ks < 4; ks++) {
                const uint2 A0 = *(const uint2*)(Ps + (R0 + g) * RW + ks * 8 + 2 * t);
                const uint2 A1 = *(const uint2*)(Ps + (R0 + g + 8) * RW + ks * 8 + 2 * t);
#pragma unroll
                for (int nt = 0; nt < 8; nt++) {
                    const uint2 Bf =
                        *(const uint2*)(Vb + (nt * 8 + g) * RW + ks * 8 + 2 * t);
                    mma16(o[nt], A0.x, A1.x, A0.y, A1.y, Bf.x, Bf.y);
                }
            }
        }

        // ---- normalize + store ----
        const float i0 = 1.0f / l0v, i1 = 1.0f / l1v;
        const size_t out0 = base + (size_t)(qbase + R0 + g) * rs;
        const size_t out1 = base + (size_t)(qbase + R0 + g + 8) * rs;
#pragma unroll
        for (int nt = 0; nt < 8; nt++) {
            const int cc = nt * 8 + 2 * t;
            *(float2*)(Out + out0 + cc) = make_float2(o[nt][0] * i0, o[nt][1] * i0);
            *(float2*)(Out + out1 + cc) = make_float2(o[nt][2] * i1, o[nt][3] * i1);
        }
    }
}

// ---------------------------------------------------------------------------
extern "C" void kernel_launch(void* const* d_in, const int* in_sizes, int n_in,
                              void* d_out, int out_size) {
    const float* Q  = (const float*)d_in[0];
    const float* K  = (const float*)d_in[1];
    const float* V  = (const float*)d_in[2];
    const float* Wa = (const float*)d_in[3];
    const float* ba = (const float*)d_in[4];
    const float* Wo = (const float*)d_in[5];
    const float* bo = (const float*)d_in[6];
    float* Out = (float*)d_out;

    cudaFuncSetAttribute(attn_kernel, cudaFuncAttributeMaxDynamicSharedMemorySize,
                         SMEM_BYTES);

    quantum_kernel<<<NTOK / 256, 256>>>(V, K, Wa, ba, Wo, bo);
    dim3 vgrid(SS / 64, BB * HH);
    vt_kernel<<<vgrid, 256>>>();
    attn_kernel<<<148, 256, SMEM_BYTES>>>(Q, Out);
}